// round 16
// baseline (speedup 1.0000x reference)
#include <cuda_runtime.h>
#include <cstdint>

#define MAXN 250000
#define DD 128
#define HH 256

// ---------------- smem layout (byte offsets) ----------------
#define OFF_BIAS1 0        // 256 floats
#define OFF_BIAS2 1024     // 128 floats
#define OFF_AUX   1536     // kernel-specific (<= 4 KB)
#define OFF_BBUF  5632     // B ring buffer: 4 stages x up to 8 KB
#define OFF_AT    38400    // A chunk (32 KB) / layer-2 T (64 KB) shared region
#define SMEM_ALL  (OFF_AT + 65536)   // 103936 (~101.5 KB) -> 2 CTAs/SM

// ---------------- device scratch ----------------
__device__ float g_hidden[MAXN * DD];
__device__ float g_sp[MAXN * DD];
__device__ float g_sc[MAXN * DD];
__device__ int   g_cnt_self[MAXN];
__device__ int   g_cnt_par[MAXN];
__device__ float g_biasP[HH];
__device__ float g_biasC[HH];

// weights in tf32 MMA-fragment order (pair-interleaved B tiles):
// word = (k>>3)*(NT*64) + (n>>4)*128 + ((n&7)*4+(k&3))*4 + ((n>>3)&1)*2 + ((k>>2)&1)
__device__ __align__(16) uint32_t g_V1f[128 * 256];
__device__ __align__(16) uint32_t g_V2f[256 * 128];
__device__ __align__(16) uint32_t g_P1f[256 * 256];
__device__ __align__(16) uint32_t g_P2f[256 * 128];
__device__ __align__(16) uint32_t g_C1f[256 * 256];
__device__ __align__(16) uint32_t g_C2f[256 * 128];
__device__ __align__(16) uint32_t g_A1f[384 * 256];
__device__ __align__(16) uint32_t g_A2f[256 * 128];

// ---------------- helpers ----------------
__device__ __forceinline__ uint32_t tf32r(float x) {
    uint32_t y;
    asm("cvt.rna.tf32.f32 %0, %1;" : "=r"(y) : "f"(x));
    return y;
}
__device__ __forceinline__ uint32_t smem_u32(const void* p) {
    uint32_t a;
    asm("{ .reg .u64 t; cvta.to.shared.u64 t, %1; cvt.u32.u64 %0, t; }" : "=r"(a) : "l"(p));
    return a;
}
__device__ __forceinline__ void cpasync16(uint32_t dst, const void* src) {
    asm volatile("cp.async.ca.shared.global [%0], [%1], 16;" :: "r"(dst), "l"(src));
}
#define CP_COMMIT() asm volatile("cp.async.commit_group;")
#define CP_WAIT(n)  asm volatile("cp.async.wait_group %0;" :: "n"(n))

__device__ __forceinline__ void mma_tf32(float* d, const uint32_t* a, uint32_t b0, uint32_t b1) {
    asm volatile(
        "mma.sync.aligned.m16n8k8.row.col.f32.tf32.tf32.f32 "
        "{%0,%1,%2,%3}, {%4,%5,%6,%7}, {%8,%9}, {%0,%1,%2,%3};"
        : "+f"(d[0]), "+f"(d[1]), "+f"(d[2]), "+f"(d[3])
        : "r"(a[0]), "r"(a[1]), "r"(a[2]), "r"(a[3]), "r"(b0), "r"(b1));
}
__device__ __forceinline__ void red_add_v2(float* p, float x, float y) {
    asm volatile("red.global.add.v2.f32 [%0], {%1,%2};" :: "l"(p), "f"(x), "f"(y) : "memory");
}

// A region granule addressing (16B granules; ldmatrix-compatible).
// tile = m16-tile: 32 granules = 4 "b16 matrices" x 8 rows.
// swizzle: row ^ (mat*2) ^ (tile>>2)  -> conflict-free STS.128 staging AND ldmatrix loads.
__device__ __forceinline__ uint32_t granuleAddr(int tile, int mat, int row) {
    int g = mat * 8 + ((row ^ (mat * 2) ^ (tile >> 2)) & 7);
    return (uint32_t)OFF_AT + (uint32_t)tile * 512u + (uint32_t)g * 16u;
}

// store float4 (row r in [0,64), chunk cols k0..k0+3) as ONE STS.128
__device__ __forceinline__ void stA4(char* sm, int r, int k0, float4 v) {
    int tile = (k0 >> 3) * 4 + (r >> 4);
    int mat = ((k0 & 4) ? 2 : 0) + ((r & 8) ? 1 : 0);
    uint32_t base = granuleAddr(tile, mat, r & 7);
    uint4 w = make_uint4(tf32r(v.x), tf32r(v.y), tf32r(v.z), tf32r(v.w));
    *(uint4*)(sm + base) = w;
}

// ---------------- tf32 GEMM (accumulating): 64 rows x (NT*8) cols, K = KS*8 ----------------
// 8 warps as 2(m) x 4(n); warp tile m32 x n(NTW*8); accum d[2][NTW][4] (no zeroing here).
// A via ldmatrix.x4 from granule layout; B via 4-stage cp.async ring, pair-wise pipelined:
// ONE CP_WAIT + ONE __syncthreads per 2 ksteps. Caller syncs after staging A. KS even.
template <int KS, int NT, int NTW>
__device__ void gemm_acc(char* sm, uint32_t sbase, const uint32_t* gB, float (&d)[2][NTW][4]) {
    const int tid = threadIdx.x, wid = tid >> 5, lane = tid & 31;
    const int warpM = wid >> 2, warpG = wid & 3;
    const int chunkB = NT * 256;                 // bytes per k8 chunk
    const int cpN = chunkB / (16 * 256);         // cp.async per thread (2 or 1)
    const int lmat = lane >> 3, lrow = lane & 7;
    // prologue: ksteps 0,1 -> stages 0,1 (one commit group per pair)
#pragma unroll
    for (int s = 0; s < 2; s++) {
        uint32_t dst = sbase + OFF_BBUF + (uint32_t)s * chunkB;
        const char* src = (const char*)gB + (size_t)s * chunkB;
#pragma unroll
        for (int i = 0; i < cpN; i++) {
            int f = tid + i * 256;
            cpasync16(dst + f * 16, src + f * 16);
        }
    }
    CP_COMMIT();
    for (int j = 0; j < KS / 2; j++) {
        const int t0 = 2 * j;
        // A prefetch for both ksteps of this pair (A region static: safe before wait)
        uint32_t a[2][2][4];
#pragma unroll
        for (int s = 0; s < 2; s++) {
#pragma unroll
            for (int mt = 0; mt < 2; mt++) {
                int tile = (t0 + s) * 4 + warpM * 2 + mt;
                uint32_t addr = sbase + granuleAddr(tile, lmat, lrow);
                asm volatile("ldmatrix.sync.aligned.m8n8.x4.shared.b16 {%0,%1,%2,%3}, [%4];"
                             : "=r"(a[s][mt][0]), "=r"(a[s][mt][1]),
                               "=r"(a[s][mt][2]), "=r"(a[s][mt][3])
                             : "r"(addr));
            }
        }
        CP_WAIT(0);
        __syncthreads();
        if (j + 1 < KS / 2) {
            // issue next pair (stages (t0+2)%4,(t0+3)%4 — last read at pair j-1, ordered by sync)
#pragma unroll
            for (int s = 0; s < 2; s++) {
                int tn = t0 + 2 + s;
                uint32_t dst = sbase + OFF_BBUF + (uint32_t)(tn & 3) * chunkB;
                const char* src = (const char*)gB + (size_t)tn * chunkB;
#pragma unroll
                for (int i = 0; i < cpN; i++) {
                    int f = tid + i * 256;
                    cpasync16(dst + f * 16, src + f * 16);
                }
            }
            CP_COMMIT();
        }
#pragma unroll
        for (int s = 0; s < 2; s++) {
            uint32_t bbase = sbase + OFF_BBUF + (uint32_t)((t0 + s) & 3) * chunkB;
#pragma unroll
            for (int jp = 0; jp < NTW / 2; jp++) {
                uint32_t baddr = bbase + (uint32_t)((warpG * (NTW / 2) + jp) * 128 + lane * 4) * 4u;
                uint4 vb;
                asm volatile("ld.shared.v4.u32 {%0,%1,%2,%3}, [%4];"
                             : "=r"(vb.x), "=r"(vb.y), "=r"(vb.z), "=r"(vb.w) : "r"(baddr));
#pragma unroll
                for (int mt = 0; mt < 2; mt++) {
                    mma_tf32(d[mt][2 * jp],     a[s][mt], vb.x, vb.y);
                    mma_tf32(d[mt][2 * jp + 1], a[s][mt], vb.z, vb.w);
                }
            }
        }
    }
}

// layer-1 epilogue: relu(+bias1) -> layer-2 A granules at OFF_AT (overwrites A chunk region)
__device__ void epilogue1_T(char* sm, float (&d)[2][8][4], const float* b1) {
    const int tid = threadIdx.x, wid = tid >> 5, lane = tid & 31;
    const int warpM = wid >> 2, warpG = wid & 3;
    const int g8 = lane >> 2, tig = lane & 3;
    __syncthreads();  // all layer-1 A/B reads done
#pragma unroll
    for (int mt = 0; mt < 2; mt++) {
        int rq = warpM * 2 + mt;      // r>>4 of output rows
#pragma unroll
        for (int j = 0; j < 8; j++) {
            int c = warpG * 64 + j * 8 + tig * 2;
            float v00 = fmaxf(d[mt][j][0] + b1[c],     0.f);
            float v01 = fmaxf(d[mt][j][1] + b1[c + 1], 0.f);
            float v10 = fmaxf(d[mt][j][2] + b1[c],     0.f);
            float v11 = fmaxf(d[mt][j][3] + b1[c + 1], 0.f);
            int tile = (c >> 3) * 4 + rq;
            int mat0 = (c & 4) ? 2 : 0;          // rows r0 (rbit=0)
            uint32_t a0 = granuleAddr(tile, mat0, g8) + (uint32_t)(c & 3) * 4u;
            *(uint2*)(sm + a0) = make_uint2(tf32r(v00), tf32r(v01));
            uint32_t a1 = granuleAddr(tile, mat0 + 1, g8) + (uint32_t)(c & 3) * 4u;
            *(uint2*)(sm + a1) = make_uint2(tf32r(v10), tf32r(v11));
        }
    }
    __syncthreads();
}

// ---------------- prep kernels ----------------
__global__ void prep_w(
    const float* __restrict__ V1, const float* __restrict__ V2,
    const float* __restrict__ P1, const float* __restrict__ P2,
    const float* __restrict__ C1, const float* __restrict__ C2,
    const float* __restrict__ A1, const float* __restrict__ A2,
    uint32_t* __restrict__ o1, uint32_t* __restrict__ o2,
    uint32_t* __restrict__ o3, uint32_t* __restrict__ o4,
    uint32_t* __restrict__ o5, uint32_t* __restrict__ o6,
    uint32_t* __restrict__ o7, uint32_t* __restrict__ o8,
    const int* __restrict__ si, const int* __restrict__ pi,
    int* __restrict__ cs, int* __restrict__ cp, int E) {
    int gid = blockIdx.x * blockDim.x + threadIdx.x;
    const int T0 = 32768, T1 = 65536, T2 = 131072, T3 = 163840;
    const int T4 = 229376, T5 = 262144, T6 = 360448, T7 = 393216;
    if (gid < T7) {
        const float* W; uint32_t* O; int N, i;
        if (gid < T0)      { W = V1; O = o1; N = 256; i = gid; }
        else if (gid < T1) { W = V2; O = o2; N = 128; i = gid - T0; }
        else if (gid < T2) { W = P1; O = o3; N = 256; i = gid - T1; }
        else if (gid < T3) { W = P2; O = o4; N = 128; i = gid - T2; }
        else if (gid < T4) { W = C1; O = o5; N = 256; i = gid - T3; }
        else if (gid < T5) { W = C2; O = o6; N = 128; i = gid - T4; }
        else if (gid < T6) { W = A1; O = o7; N = 256; i = gid - T5; }
        else               { W = A2; O = o8; N = 128; i = gid - T6; }
        int k = i / N, n = i - k * N;
        int NT = N >> 3;
        int wi = (k >> 3) * (NT * 64) + (n >> 4) * 128 + ((n & 7) * 4 + (k & 3)) * 4
               + (((n >> 3) & 1) ? 2 : 0) + ((k >> 2) & 1);
        O[wi] = tf32r(W[i]);
    } else {
        int e = gid - T7;
        if (e < E) {
            atomicAdd(&cs[si[e]], 1);
            atomicAdd(&cp[pi[e]], 1);
        }
    }
}

__global__ void prep_bias(const float* __restrict__ Ew1, const float* __restrict__ Eb1,
                          const float* __restrict__ Ew2, const float* __restrict__ Eb2,
                          const float* __restrict__ Pw1, const float* __restrict__ Pb1,
                          const float* __restrict__ Cw1, const float* __restrict__ Cb1,
                          float* __restrict__ biasP, float* __restrict__ biasC) {
    __shared__ float hin[HH], hout[HH], ein[DD], eout[DD];
    int t = threadIdx.x;
    if (t < HH) {
        hin[t]  = fmaxf(Ew1[t] + Eb1[t], 0.f);
        hout[t] = fmaxf(Eb1[t], 0.f);
    }
    __syncthreads();
    if (t < DD) {
        float si = Eb2[t], so = Eb2[t];
        for (int j = 0; j < HH; j++) {
            si += hin[j]  * Ew2[j * DD + t];
            so += hout[j] * Ew2[j * DD + t];
        }
        ein[t]  = fmaxf(si, 0.f);
        eout[t] = fmaxf(so, 0.f);
    }
    __syncthreads();
    if (t < HH) {
        float bp = Pb1[t], bc = Cb1[t];
        for (int d = 0; d < DD; d++) {
            bp += eout[d] * Pw1[(2 * DD + d) * HH + t];
            bc += ein[d]  * Cw1[(2 * DD + d) * HH + t];
        }
        biasP[t] = bp;
        biasC[t] = bc;
    }
}

// ---------------- layer-2 ----------------
__device__ __forceinline__ void run_layer2(char* sm, uint32_t sbase,
                                           const uint32_t* w2f, float (&d2)[2][4][4]) {
#pragma unroll
    for (int a = 0; a < 2; a++)
#pragma unroll
        for (int b = 0; b < 4; b++)
#pragma unroll
            for (int c = 0; c < 4; c++) d2[a][b][c] = 0.f;
    gemm_acc<32, 16, 4>(sm, sbase, w2f, d2);
}

// ---------------- kernel: hidden = MLP_V(batch_token) ----------------
__global__ __launch_bounds__(256, 2) void mlp_v_tf(
    const float* __restrict__ x,
    const float* __restrict__ Vb1, const float* __restrict__ Vb2,
    float* __restrict__ hidden, int Nn) {
    extern __shared__ char sm[];
    uint32_t sbase = smem_u32(sm);
    const int tid = threadIdx.x, wid = tid >> 5, lane = tid & 31;
    if (tid < 256) ((float*)(sm + OFF_BIAS1))[tid] = Vb1[tid];
    if (tid < 128) ((float*)(sm + OFF_BIAS2))[tid] = Vb2[tid];
    const int i0 = blockIdx.x * 64;
#pragma unroll 4
    for (int it = 0; it < 8; it++) {
        int lin = tid + it * 256;
        int r = lin >> 5, q = lin & 31, k0 = q * 4;
        int node = i0 + r;
        float4 v = make_float4(0.f, 0.f, 0.f, 0.f);
        if (node < Nn) v = *(const float4*)(x + (size_t)node * 128 + k0);
        stA4(sm, r, k0, v);
    }
    __syncthreads();
    float d[2][8][4];
#pragma unroll
    for (int a = 0; a < 2; a++)
#pragma unroll
        for (int b = 0; b < 8; b++)
#pragma unroll
            for (int c = 0; c < 4; c++) d[a][b][c] = 0.f;
    gemm_acc<16, 32, 8>(sm, sbase, g_V1f, d);
    epilogue1_T(sm, d, (const float*)(sm + OFF_BIAS1));
    float d2[2][4][4];
    run_layer2(sm, sbase, g_V2f, d2);
    const float* b2 = (const float*)(sm + OFF_BIAS2);
    const int warpM = wid >> 2, warpG = wid & 3, g8 = lane >> 2, tig = lane & 3;
#pragma unroll
    for (int mt = 0; mt < 2; mt++) {
        int r0 = warpM * 32 + mt * 16 + g8;
        int n0 = i0 + r0, n1 = i0 + r0 + 8;
#pragma unroll
        for (int j = 0; j < 4; j++) {
            int c = warpG * 32 + j * 8 + tig * 2;
            if (n0 < Nn) {
                float2 o = make_float2(fmaxf(d2[mt][j][0] + b2[c], 0.f),
                                       fmaxf(d2[mt][j][1] + b2[c + 1], 0.f));
                *(float2*)(hidden + (size_t)n0 * 128 + c) = o;
            }
            if (n1 < Nn) {
                float2 o = make_float2(fmaxf(d2[mt][j][2] + b2[c], 0.f),
                                       fmaxf(d2[mt][j][3] + b2[c + 1], 0.f));
                *(float2*)(hidden + (size_t)n1 * 128 + c) = o;
            }
        }
    }
}

// ---------------- kernel: edge MLPs + scatter ----------------
__device__ __forceinline__ void stage_gather(char* sm, const float* __restrict__ hidden,
                                             const int* idx) {
    const int tid = threadIdx.x;
#pragma unroll 4
    for (int it = 0; it < 8; it++) {
        int lin = tid + it * 256;
        int r = lin >> 5, q = lin & 31, k0 = q * 4;
        int i = idx[r];
        float4 v = make_float4(0.f, 0.f, 0.f, 0.f);
        if (i >= 0) v = *(const float4*)(hidden + (size_t)i * 128 + k0);
        stA4(sm, r, k0, v);
    }
}

__device__ void edge_mlp_pass(char* sm, uint32_t sbase,
                              const float* __restrict__ hidden,
                              const int* firstIdx, const int* secondIdx,
                              const uint32_t* w1f, const uint32_t* w2f,
                              const float* b1, const float* b2,
                              const int* scatIdx, float* dst) {
    const int tid = threadIdx.x, wid = tid >> 5, lane = tid & 31;
    float d[2][8][4];
#pragma unroll
    for (int a = 0; a < 2; a++)
#pragma unroll
        for (int b = 0; b < 8; b++)
#pragma unroll
            for (int c = 0; c < 4; c++) d[a][b][c] = 0.f;
    stage_gather(sm, hidden, firstIdx);
    __syncthreads();
    gemm_acc<16, 32, 8>(sm, sbase, w1f, d);
    __syncthreads();
    stage_gather(sm, hidden, secondIdx);
    __syncthreads();
    gemm_acc<16, 32, 8>(sm, sbase, w1f + 16 * 32 * 64, d);
    epilogue1_T(sm, d, b1);
    float d2[2][4][4];
    run_layer2(sm, sbase, w2f, d2);
    const int warpM = wid >> 2, warpG = wid & 3, g8 = lane >> 2, tig = lane & 3;
#pragma unroll
    for (int mt = 0; mt < 2; mt++) {
        int r0 = warpM * 32 + mt * 16 + g8;
        int ia = scatIdx[r0], ib = scatIdx[r0 + 8];
#pragma unroll
        for (int j = 0; j < 4; j++) {
            int c = warpG * 32 + j * 8 + tig * 2;
            if (ia >= 0)
                red_add_v2(dst + (size_t)ia * 128 + c,
                           fmaxf(d2[mt][j][0] + b2[c], 0.f),
                           fmaxf(d2[mt][j][1] + b2[c + 1], 0.f));
            if (ib >= 0)
                red_add_v2(dst + (size_t)ib * 128 + c,
                           fmaxf(d2[mt][j][2] + b2[c], 0.f),
                           fmaxf(d2[mt][j][3] + b2[c + 1], 0.f));
        }
    }
    __syncthreads();   // scatter done; safe to re-stage A region next
}

__global__ __launch_bounds__(256, 2) void edge_tf(
    const float* __restrict__ hidden,
    const int* __restrict__ self_idx, const int* __restrict__ parent_idx,
    const float* __restrict__ biasP, const float* __restrict__ Pb2,
    const float* __restrict__ biasC, const float* __restrict__ Cb2,
    float* __restrict__ sp, float* __restrict__ sc, int E) {
    extern __shared__ char sm[];
    uint32_t sbase = smem_u32(sm);
    const int tid = threadIdx.x;
    int* sIdx = (int*)(sm + OFF_AUX);                 // 64 ints
    int* pIdx = (int*)(sm + OFF_AUX + 256);           // 64 ints
    float* bC1 = (float*)(sm + OFF_AUX + 512);        // 256 f
    float* bC2 = (float*)(sm + OFF_AUX + 1536);       // 128 f
    const int e0 = blockIdx.x * 64;
    if (tid < 64) {
        int e = e0 + tid;
        sIdx[tid] = (e < E) ? self_idx[e] : -1;
        pIdx[tid] = (e < E) ? parent_idx[e] : -1;
    }
    if (tid < 256) {
        ((float*)(sm + OFF_BIAS1))[tid] = biasP[tid];
        bC1[tid] = biasC[tid];
    }
    if (tid < 128) {
        ((float*)(sm + OFF_BIAS2))[tid] = Pb2[tid];
        bC2[tid] = Cb2[tid];
    }
    __syncthreads();
    // MLP_P: input [parent | self], scatter by self
    edge_mlp_pass(sm, sbase, hidden, pIdx, sIdx, g_P1f, g_P2f,
                  (const float*)(sm + OFF_BIAS1), (const float*)(sm + OFF_BIAS2), sIdx, sp);
    // MLP_C: input [self | parent], scatter by parent
    edge_mlp_pass(sm, sbase, hidden, sIdx, pIdx, g_C1f, g_C2f, bC1, bC2, pIdx, sc);
}

// ---------------- kernel: node aggregation ----------------
__global__ __launch_bounds__(256, 2) void node_tf(
    const float* __restrict__ hidden,
    const float* __restrict__ sp, const float* __restrict__ sc,
    const int* __restrict__ cntS, const int* __restrict__ cntP,
    const float* __restrict__ root_mask, const float* __restrict__ leaf_mask,
    const float* __restrict__ start_tok, const float* __restrict__ end_tok,
    const float* __restrict__ Ab1, const float* __restrict__ Ab2,
    float* __restrict__ out, int Nn) {
    extern __shared__ char sm[];
    uint32_t sbase = smem_u32(sm);
    const int tid = threadIdx.x, wid = tid >> 5, lane = tid & 31;
    float4* rowsc = (float4*)(sm + OFF_AUX);          // 64 * 16 B
    float* stok = (float*)(sm + OFF_AUX + 1024);      // 512 B
    float* etok = (float*)(sm + OFF_AUX + 1536);      // 512 B
    const int i0 = blockIdx.x * 64;
    if (tid < 64) {
        int node = i0 + tid;
        float4 rs = make_float4(1.f, 1.f, 0.f, 0.f);
        if (node < Nn) {
            int csv = cntS[node]; if (csv < 1) csv = 1;
            int cpv = cntP[node]; if (cpv < 1) cpv = 1;
            rs = make_float4(1.0f / (float)csv, 1.0f / (float)cpv,
                             root_mask[node], leaf_mask[node]);
        }
        rowsc[tid] = rs;
    }
    if (tid < 128) {
        stok[tid] = start_tok[tid];
        etok[tid] = end_tok[tid];
    }
    if (tid < 256) ((float*)(sm + OFF_BIAS1))[tid] = Ab1[tid];
    if (tid < 128) ((float*)(sm + OFF_BIAS2))[tid] = Ab2[tid];
    __syncthreads();
    float d[2][8][4];
#pragma unroll
    for (int a = 0; a < 2; a++)
#pragma unroll
        for (int b = 0; b < 8; b++)
#pragma unroll
            for (int c = 0; c < 4; c++) d[a][b][c] = 0.f;
    // chunk 0: hidden
#pragma unroll 4
    for (int it = 0; it < 8; it++) {
        int lin = tid + it * 256;
        int r = lin >> 5, q = lin & 31, k0 = q * 4;
        int node = i0 + r;
        float4 v = make_float4(0.f, 0.f, 0.f, 0.f);
        if (node < Nn) v = *(const float4*)(hidden + (size_t)node * 128 + k0);
        stA4(sm, r, k0, v);
    }
    __syncthreads();
    gemm_acc<16, 32, 8>(sm, sbase, g_A1f, d);
    __syncthreads();
    // chunk 1: Sp scaled + root token
#pragma unroll 4
    for (int it = 0; it < 8; it++) {
        int lin = tid + it * 256;
        int r = lin >> 5, q = lin & 31, k0 = q * 4;
        int node = i0 + r;
        float4 v = make_float4(0.f, 0.f, 0.f, 0.f);
        if (node < Nn) {
            float4 s = *(const float4*)(sp + (size_t)node * 128 + k0);
            float4 rs = rowsc[r];
            v.x = s.x * rs.x + rs.z * stok[k0 + 0];
            v.y = s.y * rs.x + rs.z * stok[k0 + 1];
            v.z = s.z * rs.x + rs.z * stok[k0 + 2];
            v.w = s.w * rs.x + rs.z * stok[k0 + 3];
        }
        stA4(sm, r, k0, v);
    }
    __syncthreads();
    gemm_acc<16, 32, 8>(sm, sbase, g_A1f + 16 * 32 * 64, d);
    __syncthreads();
    // chunk 2: Sc scaled + leaf token
#pragma unroll 4
    for (int it = 0; it < 8; it++) {
        int lin = tid + it * 256;
        int r = lin >> 5, q = lin & 31, k0 = q * 4;
        int node = i0 + r;
        float4 v = make_float4(0.f, 0.f, 0.f, 0.f);
        if (node < Nn) {
            float4 s = *(const float4*)(sc + (size_t)node * 128 + k0);
            float4 rs = rowsc[r];
            v.x = s.x * rs.y + rs.w * etok[k0 + 0];
            v.y = s.y * rs.y + rs.w * etok[k0 + 1];
            v.z = s.z * rs.y + rs.w * etok[k0 + 2];
            v.w = s.w * rs.y + rs.w * etok[k0 + 3];
        }
        stA4(sm, r, k0, v);
    }
    __syncthreads();
    gemm_acc<16, 32, 8>(sm, sbase, g_A1f + 32 * 32 * 64, d);
    epilogue1_T(sm, d, (const float*)(sm + OFF_BIAS1));
    float d2[2][4][4];
    run_layer2(sm, sbase, g_A2f, d2);
    const float* b2 = (const float*)(sm + OFF_BIAS2);
    const int warpM = wid >> 2, warpG = wid & 3, g8 = lane >> 2, tig = lane & 3;
#pragma unroll
    for (int mt = 0; mt < 2; mt++) {
        int r0 = warpM * 32 + mt * 16 + g8;
        int n0 = i0 + r0, n1 = i0 + r0 + 8;
#pragma unroll
        for (int j = 0; j < 4; j++) {
            int c = warpG * 32 + j * 8 + tig * 2;
            if (n0 < Nn) {
                float2 h = *(const float2*)(hidden + (size_t)n0 * 128 + c);
                float2 o = make_float2(h.x + fmaxf(d2[mt][j][0] + b2[c], 0.f),
                                       h.y + fmaxf(d2[mt][j][1] + b2[c + 1], 0.f));
                *(float2*)(out + (size_t)n0 * 128 + c) = o;
            }
            if (n1 < Nn) {
                float2 h = *(const float2*)(hidden + (size_t)n1 * 128 + c);
                float2 o = make_float2(h.x + fmaxf(d2[mt][j][2] + b2[c], 0.f),
                                       h.y + fmaxf(d2[mt][j][3] + b2[c + 1], 0.f));
                *(float2*)(out + (size_t)n1 * 128 + c) = o;
            }
        }
    }
}

// ---------------- host launch ----------------
extern "C" void kernel_launch(void* const* d_in, const int* in_sizes, int n_in,
                              void* d_out, int out_size) {
    const float* batch_token = (const float*)d_in[0];
    const int*   self_idx    = (const int*)d_in[1];
    const int*   parent_idx  = (const int*)d_in[2];
    const float* root_mask   = (const float*)d_in[3];
    const float* leaf_mask   = (const float*)d_in[4];
    const float* start_tok   = (const float*)d_in[5];
    const float* end_tok     = (const float*)d_in[6];
    const float* Vw1 = (const float*)d_in[7];
    const float* Vb1 = (const float*)d_in[8];
    const float* Vw2 = (const float*)d_in[9];
    const float* Vb2 = (const float*)d_in[10];
    const float* Ew1 = (const float*)d_in[11];
    const float* Eb1 = (const float*)d_in[12];
    const float* Ew2 = (const float*)d_in[13];
    const float* Eb2 = (const float*)d_in[14];
    const float* Pw1 = (const float*)d_in[15];
    const float* Pb1 = (const float*)d_in[16];
    const float* Pw2 = (const float*)d_in[17];
    const float* Pb2 = (const float*)d_in[18];
    const float* Cw1 = (const float*)d_in[19];
    const float* Cb1 = (const float*)d_in[20];
    const float* Cw2 = (const float*)d_in[21];
    const float* Cb2 = (const float*)d_in[22];
    const float* Aw1 = (const float*)d_in[23];
    const float* Ab1 = (const float*)d_in[24];
    const float* Aw2 = (const float*)d_in[25];
    const float* Ab2 = (const float*)d_in[26];

    const int Nn = in_sizes[0] / 128;
    const int E  = in_sizes[1];

    float *hid, *sp, *sc, *bP, *bC;
    int *cs, *cp;
    cudaGetSymbolAddress((void**)&hid, g_hidden);
    cudaGetSymbolAddress((void**)&sp,  g_sp);
    cudaGetSymbolAddress((void**)&sc,  g_sc);
    cudaGetSymbolAddress((void**)&cs,  g_cnt_self);
    cudaGetSymbolAddress((void**)&cp,  g_cnt_par);
    cudaGetSymbolAddress((void**)&bP,  g_biasP);
    cudaGetSymbolAddress((void**)&bC,  g_biasC);
    uint32_t *v1, *v2, *p1, *p2, *c1, *c2, *a1, *a2;
    cudaGetSymbolAddress((void**)&v1, g_V1f);
    cudaGetSymbolAddress((void**)&v2, g_V2f);
    cudaGetSymbolAddress((void**)&p1, g_P1f);
    cudaGetSymbolAddress((void**)&p2, g_P2f);
    cudaGetSymbolAddress((void**)&c1, g_C1f);
    cudaGetSymbolAddress((void**)&c2, g_C2f);
    cudaGetSymbolAddress((void**)&a1, g_A1f);
    cudaGetSymbolAddress((void**)&a2, g_A2f);

    cudaFuncSetAttribute(mlp_v_tf, cudaFuncAttributeMaxDynamicSharedMemorySize, SMEM_ALL);
    cudaFuncSetAttribute(edge_tf,  cudaFuncAttributeMaxDynamicSharedMemorySize, SMEM_ALL);
    cudaFuncSetAttribute(node_tf,  cudaFuncAttributeMaxDynamicSharedMemorySize, SMEM_ALL);

    cudaMemsetAsync(cs, 0, (size_t)Nn * sizeof(int));
    cudaMemsetAsync(cp, 0, (size_t)Nn * sizeof(int));

    // launch #1: weight conversions + degree counts
    {
        const int total = 393216 + E;
        prep_w<<<(total + 255) / 256, 256>>>(Vw1, Vw2, Pw1, Pw2, Cw1, Cw2, Aw1, Aw2,
                                             v1, v2, p1, p2, c1, c2, a1, a2,
                                             self_idx, parent_idx, cs, cp, E);
    }
    // launch #2
    prep_bias<<<1, 256>>>(Ew1, Eb1, Ew2, Eb2, Pw1, Pb1, Cw1, Cb1, bP, bC);

    const int gN = (Nn + 63) / 64;
    const int gE = (E + 63) / 64;
    // launch #3
    mlp_v_tf<<<gN, 256, SMEM_ALL>>>(batch_token, Vb1, Vb2, hid, Nn);

    for (int hop = 0; hop < 3; hop++) {
        cudaMemsetAsync(sp, 0, (size_t)Nn * 128 * sizeof(float));
        cudaMemsetAsync(sc, 0, (size_t)Nn * 128 * sizeof(float));
        // launches #4/#5 (hop0), #6 = edge (hop1) <- ncu capture target
        edge_tf<<<gE, 256, SMEM_ALL>>>(hid, self_idx, parent_idx,
                                       bP, Pb2, bC, Cb2, sp, sc, E);
        float* o = (hop == 2) ? (float*)d_out : hid;
        node_tf<<<gN, 256, SMEM_ALL>>>(hid, sp, sc, cs, cp,
                                       root_mask, leaf_mask, start_tok, end_tok,
                                       Ab1, Ab2, o, Nn);
    }
}

// round 17
// speedup vs baseline: 1.6019x; 1.6019x over previous
#include <cuda_runtime.h>
#include <cuda_fp16.h>
#include <cstdint>

#define MAXN 250000
#define DD 128
#define HH 256

// ---------------- smem layout (byte offsets) ----------------
#define OFF_BIAS1 0        // 256 floats
#define OFF_BIAS2 1024     // 128 floats
#define OFF_AUX   1536     // kernel-specific (<= 4 KB)
#define OFF_BBUF  5632     // B ring buffer: 4 stages x up to 8 KB
#define OFF_AT    38400    // A chunk (16 KB) / layer-2 T (32 KB) shared region
#define SMEM_ALL  (OFF_AT + 32768)   // 71168 (~69.5 KB) -> 2 CTAs/SM (RF-capped)

// ---------------- device scratch ----------------
__device__ float g_hidden[MAXN * DD];
__device__ float g_sp[MAXN * DD];
__device__ float g_sc[MAXN * DD];
__device__ int   g_cnt_self[MAXN];
__device__ int   g_cnt_par[MAXN];
__device__ float g_biasP[HH];
__device__ float g_biasC[HH];

// weights as fp16 pairs (one u32 = half2 {k, k+1}) in m16n8k16 B-fragment order:
// word = (k>>4)*(NT*64) + (n>>4)*128 + ((n&7)*4 + ((k>>1)&3))*4 + ((n>>3)&1)*2 + ((k>>3)&1)
__device__ __align__(16) uint32_t g_V1f[128 * 256 / 2];
__device__ __align__(16) uint32_t g_V2f[256 * 128 / 2];
__device__ __align__(16) uint32_t g_P1f[256 * 256 / 2];
__device__ __align__(16) uint32_t g_P2f[256 * 128 / 2];
__device__ __align__(16) uint32_t g_C1f[256 * 256 / 2];
__device__ __align__(16) uint32_t g_C2f[256 * 128 / 2];
__device__ __align__(16) uint32_t g_A1f[384 * 256 / 2];
__device__ __align__(16) uint32_t g_A2f[256 * 128 / 2];

// ---------------- helpers ----------------
__device__ __forceinline__ uint32_t pack_h2(float a, float b) {
    __half2 h = __floats2half2_rn(a, b);
    return *(uint32_t*)&h;
}
__device__ __forceinline__ uint32_t smem_u32(const void* p) {
    uint32_t a;
    asm("{ .reg .u64 t; cvta.to.shared.u64 t, %1; cvt.u32.u64 %0, t; }" : "=r"(a) : "l"(p));
    return a;
}
__device__ __forceinline__ void cpasync16(uint32_t dst, const void* src) {
    asm volatile("cp.async.ca.shared.global [%0], [%1], 16;" :: "r"(dst), "l"(src));
}
#define CP_COMMIT() asm volatile("cp.async.commit_group;")
#define CP_WAIT(n)  asm volatile("cp.async.wait_group %0;" :: "n"(n))

__device__ __forceinline__ void mma_f16(float* d, const uint32_t* a, uint32_t b0, uint32_t b1) {
    asm volatile(
        "mma.sync.aligned.m16n8k16.row.col.f32.f16.f16.f32 "
        "{%0,%1,%2,%3}, {%4,%5,%6,%7}, {%8,%9}, {%0,%1,%2,%3};"
        : "+f"(d[0]), "+f"(d[1]), "+f"(d[2]), "+f"(d[3])
        : "r"(a[0]), "r"(a[1]), "r"(a[2]), "r"(a[3]), "r"(b0), "r"(b1));
}
__device__ __forceinline__ void red_add_v2(float* p, float x, float y) {
    asm volatile("red.global.add.v2.f32 [%0], {%1,%2};" :: "l"(p), "f"(x), "f"(y) : "memory");
}

// A/T region granule addressing (16B granules = 8 fp16 = one 8x8.b16 matrix row).
// tile = 16rows x 16k fp16 = 512 B, 32 granules = 4 matrices x 8 rows.
// swizzle keeps staging STS.128, epilogue STS.32 and ldmatrix all conflict-free.
__device__ __forceinline__ uint32_t granuleAddr(int tile, int mat, int row) {
    int g = mat * 8 + ((row ^ (mat * 2) ^ (tile >> 2)) & 7);
    return (uint32_t)OFF_AT + (uint32_t)tile * 512u + (uint32_t)g * 16u;
}

// store 8 floats (row r in [0,64), chunk cols k0..k0+7, k0%8==0) as ONE STS.128 (fp16)
__device__ __forceinline__ void stA8(char* sm, int r, int k0, float4 v0, float4 v1) {
    int tile = (k0 >> 4) * 4 + (r >> 4);
    int mat = ((k0 & 8) ? 2 : 0) + ((r & 8) ? 1 : 0);
    uint32_t base = granuleAddr(tile, mat, r & 7);
    uint4 w;
    w.x = pack_h2(v0.x, v0.y);
    w.y = pack_h2(v0.z, v0.w);
    w.z = pack_h2(v1.x, v1.y);
    w.w = pack_h2(v1.z, v1.w);
    *(uint4*)(sm + base) = w;
}

// ---------------- fp16 GEMM (accumulating): 64 rows x (NT*8) cols, K = KS*16 ----------------
// 8 warps as 2(m) x 4(n); warp tile m32 x n(NTW*8); accum d[2][NTW][4] (no zeroing here).
// A via ldmatrix.x4.b16 (genuine 16x16 fp16 tiles); B via 4-stage cp.async ring,
// pair-wise pipelined: ONE CP_WAIT + ONE __syncthreads per 2 ksteps. KS even.
template <int KS, int NT, int NTW>
__device__ void gemm_acc(char* sm, uint32_t sbase, const uint32_t* gB, float (&d)[2][NTW][4]) {
    const int tid = threadIdx.x, wid = tid >> 5, lane = tid & 31;
    const int warpM = wid >> 2, warpG = wid & 3;
    const int chunkB = NT * 256;                 // bytes per k16 chunk (NT*8 cols * 16k * 2B)
    const int cpN = chunkB / (16 * 256);         // cp.async per thread (2 or 1)
    const int lmat = lane >> 3, lrow = lane & 7;
#pragma unroll
    for (int s = 0; s < 2; s++) {
        uint32_t dst = sbase + OFF_BBUF + (uint32_t)s * chunkB;
        const char* src = (const char*)gB + (size_t)s * chunkB;
#pragma unroll
        for (int i = 0; i < cpN; i++) {
            int f = tid + i * 256;
            cpasync16(dst + f * 16, src + f * 16);
        }
    }
    CP_COMMIT();
    for (int j = 0; j < KS / 2; j++) {
        const int t0 = 2 * j;
        uint32_t a[2][2][4];
#pragma unroll
        for (int s = 0; s < 2; s++) {
#pragma unroll
            for (int mt = 0; mt < 2; mt++) {
                int tile = (t0 + s) * 4 + warpM * 2 + mt;
                uint32_t addr = sbase + granuleAddr(tile, lmat, lrow);
                asm volatile("ldmatrix.sync.aligned.m8n8.x4.shared.b16 {%0,%1,%2,%3}, [%4];"
                             : "=r"(a[s][mt][0]), "=r"(a[s][mt][1]),
                               "=r"(a[s][mt][2]), "=r"(a[s][mt][3])
                             : "r"(addr));
            }
        }
        CP_WAIT(0);
        __syncthreads();
        if (j + 1 < KS / 2) {
#pragma unroll
            for (int s = 0; s < 2; s++) {
                int tn = t0 + 2 + s;
                uint32_t dst = sbase + OFF_BBUF + (uint32_t)(tn & 3) * chunkB;
                const char* src = (const char*)gB + (size_t)tn * chunkB;
#pragma unroll
                for (int i = 0; i < cpN; i++) {
                    int f = tid + i * 256;
                    cpasync16(dst + f * 16, src + f * 16);
                }
            }
            CP_COMMIT();
        }
#pragma unroll
        for (int s = 0; s < 2; s++) {
            uint32_t bbase = sbase + OFF_BBUF + (uint32_t)((t0 + s) & 3) * chunkB;
#pragma unroll
            for (int jp = 0; jp < NTW / 2; jp++) {
                uint32_t baddr = bbase + (uint32_t)((warpG * (NTW / 2) + jp) * 128 + lane * 4) * 4u;
                uint4 vb;
                asm volatile("ld.shared.v4.u32 {%0,%1,%2,%3}, [%4];"
                             : "=r"(vb.x), "=r"(vb.y), "=r"(vb.z), "=r"(vb.w) : "r"(baddr));
#pragma unroll
                for (int mt = 0; mt < 2; mt++) {
                    mma_f16(d[mt][2 * jp],     a[s][mt], vb.x, vb.y);
                    mma_f16(d[mt][2 * jp + 1], a[s][mt], vb.z, vb.w);
                }
            }
        }
    }
}

// layer-1 epilogue: relu(+bias1) -> layer-2 A granules (fp16) at OFF_AT
__device__ void epilogue1_T(char* sm, float (&d)[2][8][4], const float* b1) {
    const int tid = threadIdx.x, wid = tid >> 5, lane = tid & 31;
    const int warpM = wid >> 2, warpG = wid & 3;
    const int g8 = lane >> 2, tig = lane & 3;
    __syncthreads();  // all layer-1 A/B reads done
#pragma unroll
    for (int mt = 0; mt < 2; mt++) {
        int rq = warpM * 2 + mt;      // (row>>4) of output rows
#pragma unroll
        for (int j = 0; j < 8; j++) {
            int c = warpG * 64 + j * 8 + tig * 2;
            uint32_t w0 = pack_h2(fmaxf(d[mt][j][0] + b1[c], 0.f),
                                  fmaxf(d[mt][j][1] + b1[c + 1], 0.f));
            uint32_t w1 = pack_h2(fmaxf(d[mt][j][2] + b1[c], 0.f),
                                  fmaxf(d[mt][j][3] + b1[c + 1], 0.f));
            int tile = (c >> 4) * 4 + rq;
            int mat0 = (c & 8) ? 2 : 0;
            uint32_t off = (uint32_t)((c & 7) >> 1) * 4u;
            *(uint32_t*)(sm + granuleAddr(tile, mat0, g8) + off) = w0;       // rows r
            *(uint32_t*)(sm + granuleAddr(tile, mat0 + 1, g8) + off) = w1;   // rows r+8
        }
    }
    __syncthreads();
}

// ---------------- prep kernels ----------------
// converts fp32 weights to fp16-pair fragment words; also degree counts.
__global__ void prep_w(
    const float* __restrict__ V1, const float* __restrict__ V2,
    const float* __restrict__ P1, const float* __restrict__ P2,
    const float* __restrict__ C1, const float* __restrict__ C2,
    const float* __restrict__ A1, const float* __restrict__ A2,
    uint32_t* __restrict__ o1, uint32_t* __restrict__ o2,
    uint32_t* __restrict__ o3, uint32_t* __restrict__ o4,
    uint32_t* __restrict__ o5, uint32_t* __restrict__ o6,
    uint32_t* __restrict__ o7, uint32_t* __restrict__ o8,
    const int* __restrict__ si, const int* __restrict__ pi,
    int* __restrict__ cs, int* __restrict__ cp, int E) {
    int gid = blockIdx.x * blockDim.x + threadIdx.x;
    const int T0 = 16384, T1 = 32768, T2 = 65536, T3 = 81920;
    const int T4 = 114688, T5 = 131072, T6 = 180224, T7 = 196608;
    if (gid < T7) {
        const float* W; uint32_t* O; int N, i;
        if (gid < T0)      { W = V1; O = o1; N = 256; i = gid; }
        else if (gid < T1) { W = V2; O = o2; N = 128; i = gid - T0; }
        else if (gid < T2) { W = P1; O = o3; N = 256; i = gid - T1; }
        else if (gid < T3) { W = P2; O = o4; N = 128; i = gid - T2; }
        else if (gid < T4) { W = C1; O = o5; N = 256; i = gid - T3; }
        else if (gid < T5) { W = C2; O = o6; N = 128; i = gid - T4; }
        else if (gid < T6) { W = A1; O = o7; N = 256; i = gid - T5; }
        else               { W = A2; O = o8; N = 128; i = gid - T6; }
        int kp = i / N, n = i - kp * N;
        int k = kp * 2;
        float w0 = W[(size_t)k * N + n];
        float w1 = W[(size_t)(k + 1) * N + n];
        int NT = N >> 3;
        int wi = (k >> 4) * (NT * 64) + (n >> 4) * 128 + ((n & 7) * 4 + ((k >> 1) & 3)) * 4
               + (((n >> 3) & 1) ? 2 : 0) + ((k >> 3) & 1);
        O[wi] = pack_h2(w0, w1);
    } else {
        int e = gid - T7;
        if (e < E) {
            atomicAdd(&cs[si[e]], 1);
            atomicAdd(&cp[pi[e]], 1);
        }
    }
}

__global__ void prep_bias(const float* __restrict__ Ew1, const float* __restrict__ Eb1,
                          const float* __restrict__ Ew2, const float* __restrict__ Eb2,
                          const float* __restrict__ Pw1, const float* __restrict__ Pb1,
                          const float* __restrict__ Cw1, const float* __restrict__ Cb1,
                          float* __restrict__ biasP, float* __restrict__ biasC) {
    __shared__ float hin[HH], hout[HH], ein[DD], eout[DD];
    int t = threadIdx.x;
    if (t < HH) {
        hin[t]  = fmaxf(Ew1[t] + Eb1[t], 0.f);
        hout[t] = fmaxf(Eb1[t], 0.f);
    }
    __syncthreads();
    if (t < DD) {
        float si = Eb2[t], so = Eb2[t];
        for (int j = 0; j < HH; j++) {
            si += hin[j]  * Ew2[j * DD + t];
            so += hout[j] * Ew2[j * DD + t];
        }
        ein[t]  = fmaxf(si, 0.f);
        eout[t] = fmaxf(so, 0.f);
    }
    __syncthreads();
    if (t < HH) {
        float bp = Pb1[t], bc = Cb1[t];
        for (int d = 0; d < DD; d++) {
            bp += eout[d] * Pw1[(2 * DD + d) * HH + t];
            bc += ein[d]  * Cw1[(2 * DD + d) * HH + t];
        }
        biasP[t] = bp;
        biasC[t] = bc;
    }
}

// ---------------- layer-2 ----------------
__device__ __forceinline__ void run_layer2(char* sm, uint32_t sbase,
                                           const uint32_t* w2f, float (&d2)[2][4][4]) {
#pragma unroll
    for (int a = 0; a < 2; a++)
#pragma unroll
        for (int b = 0; b < 4; b++)
#pragma unroll
            for (int c = 0; c < 4; c++) d2[a][b][c] = 0.f;
    gemm_acc<16, 16, 4>(sm, sbase, w2f, d2);   // K=256 -> 16 k16-steps
}

// ---------------- kernel: hidden = MLP_V(batch_token) ----------------
__global__ __launch_bounds__(256, 2) void mlp_v_tf(
    const float* __restrict__ x,
    const float* __restrict__ Vb1, const float* __restrict__ Vb2,
    float* __restrict__ hidden, int Nn) {
    extern __shared__ char sm[];
    uint32_t sbase = smem_u32(sm);
    const int tid = threadIdx.x, wid = tid >> 5, lane = tid & 31;
    if (tid < 256) ((float*)(sm + OFF_BIAS1))[tid] = Vb1[tid];
    if (tid < 128) ((float*)(sm + OFF_BIAS2))[tid] = Vb2[tid];
    const int i0 = blockIdx.x * 64;
#pragma unroll
    for (int it = 0; it < 4; it++) {           // 1024 granules
        int g = tid + it * 256;
        int r = g >> 4, k0 = (g & 15) * 8;
        int node = i0 + r;
        float4 v0 = make_float4(0.f, 0.f, 0.f, 0.f), v1 = v0;
        if (node < Nn) {
            v0 = *(const float4*)(x + (size_t)node * 128 + k0);
            v1 = *(const float4*)(x + (size_t)node * 128 + k0 + 4);
        }
        stA8(sm, r, k0, v0, v1);
    }
    __syncthreads();
    float d[2][8][4];
#pragma unroll
    for (int a = 0; a < 2; a++)
#pragma unroll
        for (int b = 0; b < 8; b++)
#pragma unroll
            for (int c = 0; c < 4; c++) d[a][b][c] = 0.f;
    gemm_acc<8, 32, 8>(sm, sbase, g_V1f, d);   // K=128 -> 8 k16-steps
    epilogue1_T(sm, d, (const float*)(sm + OFF_BIAS1));
    float d2[2][4][4];
    run_layer2(sm, sbase, g_V2f, d2);
    const float* b2 = (const float*)(sm + OFF_BIAS2);
    const int warpM = wid >> 2, warpG = wid & 3, g8 = lane >> 2, tig = lane & 3;
#pragma unroll
    for (int mt = 0; mt < 2; mt++) {
        int r0 = warpM * 32 + mt * 16 + g8;
        int n0 = i0 + r0, n1 = i0 + r0 + 8;
#pragma unroll
        for (int j = 0; j < 4; j++) {
            int c = warpG * 32 + j * 8 + tig * 2;
            if (n0 < Nn) {
                float2 o = make_float2(fmaxf(d2[mt][j][0] + b2[c], 0.f),
                                       fmaxf(d2[mt][j][1] + b2[c + 1], 0.f));
                *(float2*)(hidden + (size_t)n0 * 128 + c) = o;
            }
            if (n1 < Nn) {
                float2 o = make_float2(fmaxf(d2[mt][j][2] + b2[c], 0.f),
                                       fmaxf(d2[mt][j][3] + b2[c + 1], 0.f));
                *(float2*)(hidden + (size_t)n1 * 128 + c) = o;
            }
        }
    }
}

// ---------------- kernel: edge MLPs + scatter ----------------
__device__ __forceinline__ void stage_gather(char* sm, const float* __restrict__ hidden,
                                             const int* idx) {
    const int tid = threadIdx.x;
#pragma unroll
    for (int it = 0; it < 4; it++) {
        int g = tid + it * 256;
        int r = g >> 4, k0 = (g & 15) * 8;
        int i = idx[r];
        float4 v0 = make_float4(0.f, 0.f, 0.f, 0.f), v1 = v0;
        if (i >= 0) {
            v0 = *(const float4*)(hidden + (size_t)i * 128 + k0);
            v1 = *(const float4*)(hidden + (size_t)i * 128 + k0 + 4);
        }
        stA8(sm, r, k0, v0, v1);
    }
}

__device__ void edge_mlp_pass(char* sm, uint32_t sbase,
                              const float* __restrict__ hidden,
                              const int* firstIdx, const int* secondIdx,
                              const uint32_t* w1f, const uint32_t* w2f,
                              const float* b1, const float* b2,
                              const int* scatIdx, float* dst) {
    const int tid = threadIdx.x, wid = tid >> 5, lane = tid & 31;
    float d[2][8][4];
#pragma unroll
    for (int a = 0; a < 2; a++)
#pragma unroll
        for (int b = 0; b < 8; b++)
#pragma unroll
            for (int c = 0; c < 4; c++) d[a][b][c] = 0.f;
    stage_gather(sm, hidden, firstIdx);
    __syncthreads();
    gemm_acc<8, 32, 8>(sm, sbase, w1f, d);
    __syncthreads();
    stage_gather(sm, hidden, secondIdx);
    __syncthreads();
    gemm_acc<8, 32, 8>(sm, sbase, w1f + 8 * 32 * 64, d);
    epilogue1_T(sm, d, b1);
    float d2[2][4][4];
    run_layer2(sm, sbase, w2f, d2);
    const int warpM = wid >> 2, warpG = wid & 3, g8 = lane >> 2, tig = lane & 3;
#pragma unroll
    for (int mt = 0; mt < 2; mt++) {
        int r0 = warpM * 32 + mt * 16 + g8;
        int ia = scatIdx[r0], ib = scatIdx[r0 + 8];
#pragma unroll
        for (int j = 0; j < 4; j++) {
            int c = warpG * 32 + j * 8 + tig * 2;
            if (ia >= 0)
                red_add_v2(dst + (size_t)ia * 128 + c,
                           fmaxf(d2[mt][j][0] + b2[c], 0.f),
                           fmaxf(d2[mt][j][1] + b2[c + 1], 0.f));
            if (ib >= 0)
                red_add_v2(dst + (size_t)ib * 128 + c,
                           fmaxf(d2[mt][j][2] + b2[c], 0.f),
                           fmaxf(d2[mt][j][3] + b2[c + 1], 0.f));
        }
    }
    __syncthreads();   // scatter done; safe to re-stage A region next
}

__global__ __launch_bounds__(256, 2) void edge_tf(
    const float* __restrict__ hidden,
    const int* __restrict__ self_idx, const int* __restrict__ parent_idx,
    const float* __restrict__ biasP, const float* __restrict__ Pb2,
    const float* __restrict__ biasC, const float* __restrict__ Cb2,
    float* __restrict__ sp, float* __restrict__ sc, int E) {
    extern __shared__ char sm[];
    uint32_t sbase = smem_u32(sm);
    const int tid = threadIdx.x;
    int* sIdx = (int*)(sm + OFF_AUX);                 // 64 ints
    int* pIdx = (int*)(sm + OFF_AUX + 256);           // 64 ints
    float* bC1 = (float*)(sm + OFF_AUX + 512);        // 256 f
    float* bC2 = (float*)(sm + OFF_AUX + 1536);       // 128 f
    const int e0 = blockIdx.x * 64;
    if (tid < 64) {
        int e = e0 + tid;
        sIdx[tid] = (e < E) ? self_idx[e] : -1;
        pIdx[tid] = (e < E) ? parent_idx[e] : -1;
    }
    if (tid < 256) {
        ((float*)(sm + OFF_BIAS1))[tid] = biasP[tid];
        bC1[tid] = biasC[tid];
    }
    if (tid < 128) {
        ((float*)(sm + OFF_BIAS2))[tid] = Pb2[tid];
        bC2[tid] = Cb2[tid];
    }
    __syncthreads();
    // MLP_P: input [parent | self], scatter by self
    edge_mlp_pass(sm, sbase, hidden, pIdx, sIdx, g_P1f, g_P2f,
                  (const float*)(sm + OFF_BIAS1), (const float*)(sm + OFF_BIAS2), sIdx, sp);
    // MLP_C: input [self | parent], scatter by parent
    edge_mlp_pass(sm, sbase, hidden, sIdx, pIdx, g_C1f, g_C2f, bC1, bC2, pIdx, sc);
}

// ---------------- kernel: node aggregation ----------------
__global__ __launch_bounds__(256, 2) void node_tf(
    const float* __restrict__ hidden,
    const float* __restrict__ sp, const float* __restrict__ sc,
    const int* __restrict__ cntS, const int* __restrict__ cntP,
    const float* __restrict__ root_mask, const float* __restrict__ leaf_mask,
    const float* __restrict__ start_tok, const float* __restrict__ end_tok,
    const float* __restrict__ Ab1, const float* __restrict__ Ab2,
    float* __restrict__ out, int Nn) {
    extern __shared__ char sm[];
    uint32_t sbase = smem_u32(sm);
    const int tid = threadIdx.x, wid = tid >> 5, lane = tid & 31;
    float4* rowsc = (float4*)(sm + OFF_AUX);          // 64 * 16 B
    float* stok = (float*)(sm + OFF_AUX + 1024);      // 512 B
    float* etok = (float*)(sm + OFF_AUX + 1536);      // 512 B
    const int i0 = blockIdx.x * 64;
    if (tid < 64) {
        int node = i0 + tid;
        float4 rs = make_float4(1.f, 1.f, 0.f, 0.f);
        if (node < Nn) {
            int csv = cntS[node]; if (csv < 1) csv = 1;
            int cpv = cntP[node]; if (cpv < 1) cpv = 1;
            rs = make_float4(1.0f / (float)csv, 1.0f / (float)cpv,
                             root_mask[node], leaf_mask[node]);
        }
        rowsc[tid] = rs;
    }
    if (tid < 128) {
        stok[tid] = start_tok[tid];
        etok[tid] = end_tok[tid];
    }
    if (tid < 256) ((float*)(sm + OFF_BIAS1))[tid] = Ab1[tid];
    if (tid < 128) ((float*)(sm + OFF_BIAS2))[tid] = Ab2[tid];
    __syncthreads();
    float d[2][8][4];
#pragma unroll
    for (int a = 0; a < 2; a++)
#pragma unroll
        for (int b = 0; b < 8; b++)
#pragma unroll
            for (int c = 0; c < 4; c++) d[a][b][c] = 0.f;
    // chunk 0: hidden
#pragma unroll
    for (int it = 0; it < 4; it++) {
        int g = tid + it * 256;
        int r = g >> 4, k0 = (g & 15) * 8;
        int node = i0 + r;
        float4 v0 = make_float4(0.f, 0.f, 0.f, 0.f), v1 = v0;
        if (node < Nn) {
            v0 = *(const float4*)(hidden + (size_t)node * 128 + k0);
            v1 = *(const float4*)(hidden + (size_t)node * 128 + k0 + 4);
        }
        stA8(sm, r, k0, v0, v1);
    }
    __syncthreads();
    gemm_acc<8, 32, 8>(sm, sbase, g_A1f, d);
    __syncthreads();
    // chunk 1: Sp scaled + root token
#pragma unroll
    for (int it = 0; it < 4; it++) {
        int g = tid + it * 256;
        int r = g >> 4, k0 = (g & 15) * 8;
        int node = i0 + r;
        float4 v0 = make_float4(0.f, 0.f, 0.f, 0.f), v1 = v0;
        if (node < Nn) {
            float4 s0 = *(const float4*)(sp + (size_t)node * 128 + k0);
            float4 s1 = *(const float4*)(sp + (size_t)node * 128 + k0 + 4);
            float4 rs = rowsc[r];
            v0.x = s0.x * rs.x + rs.z * stok[k0 + 0];
            v0.y = s0.y * rs.x + rs.z * stok[k0 + 1];
            v0.z = s0.z * rs.x + rs.z * stok[k0 + 2];
            v0.w = s0.w * rs.x + rs.z * stok[k0 + 3];
            v1.x = s1.x * rs.x + rs.z * stok[k0 + 4];
            v1.y = s1.y * rs.x + rs.z * stok[k0 + 5];
            v1.z = s1.z * rs.x + rs.z * stok[k0 + 6];
            v1.w = s1.w * rs.x + rs.z * stok[k0 + 7];
        }
        stA8(sm, r, k0, v0, v1);
    }
    __syncthreads();
    gemm_acc<8, 32, 8>(sm, sbase, g_A1f + 8 * 32 * 64, d);
    __syncthreads();
    // chunk 2: Sc scaled + leaf token
#pragma unroll
    for (int it = 0; it < 4; it++) {
        int g = tid + it * 256;
        int r = g >> 4, k0 = (g & 15) * 8;
        int node = i0 + r;
        float4 v0 = make_float4(0.f, 0.f, 0.f, 0.f), v1 = v0;
        if (node < Nn) {
            float4 s0 = *(const float4*)(sc + (size_t)node * 128 + k0);
            float4 s1 = *(const float4*)(sc + (size_t)node * 128 + k0 + 4);
            float4 rs = rowsc[r];
            v0.x = s0.x * rs.y + rs.w * etok[k0 + 0];
            v0.y = s0.y * rs.y + rs.w * etok[k0 + 1];
            v0.z = s0.z * rs.y + rs.w * etok[k0 + 2];
            v0.w = s0.w * rs.y + rs.w * etok[k0 + 3];
            v1.x = s1.x * rs.y + rs.w * etok[k0 + 4];
            v1.y = s1.y * rs.y + rs.w * etok[k0 + 5];
            v1.z = s1.z * rs.y + rs.w * etok[k0 + 6];
            v1.w = s1.w * rs.y + rs.w * etok[k0 + 7];
        }
        stA8(sm, r, k0, v0, v1);
    }
    __syncthreads();
    gemm_acc<8, 32, 8>(sm, sbase, g_A1f + 16 * 32 * 64, d);
    epilogue1_T(sm, d, (const float*)(sm + OFF_BIAS1));
    float d2[2][4][4];
    run_layer2(sm, sbase, g_A2f, d2);
    const float* b2 = (const float*)(sm + OFF_BIAS2);
    const int warpM = wid >> 2, warpG = wid & 3, g8 = lane >> 2, tig = lane & 3;
#pragma unroll
    for (int mt = 0; mt < 2; mt++) {
        int r0 = warpM * 32 + mt * 16 + g8;
        int n0 = i0 + r0, n1 = i0 + r0 + 8;
#pragma unroll
        for (int j = 0; j < 4; j++) {
            int c = warpG * 32 + j * 8 + tig * 2;
            if (n0 < Nn) {
                float2 h = *(const float2*)(hidden + (size_t)n0 * 128 + c);
                float2 o = make_float2(h.x + fmaxf(d2[mt][j][0] + b2[c], 0.f),
                                       h.y + fmaxf(d2[mt][j][1] + b2[c + 1], 0.f));
                *(float2*)(out + (size_t)n0 * 128 + c) = o;
            }
            if (n1 < Nn) {
                float2 h = *(const float2*)(hidden + (size_t)n1 * 128 + c);
                float2 o = make_float2(h.x + fmaxf(d2[mt][j][2] + b2[c], 0.f),
                                       h.y + fmaxf(d2[mt][j][3] + b2[c + 1], 0.f));
                *(float2*)(out + (size_t)n1 * 128 + c) = o;
            }
        }
    }
}

// ---------------- host launch ----------------
extern "C" void kernel_launch(void* const* d_in, const int* in_sizes, int n_in,
                              void* d_out, int out_size) {
    const float* batch_token = (const float*)d_in[0];
    const int*   self_idx    = (const int*)d_in[1];
    const int*   parent_idx  = (const int*)d_in[2];
    const float* root_mask   = (const float*)d_in[3];
    const float* leaf_mask   = (const float*)d_in[4];
    const float* start_tok   = (const float*)d_in[5];
    const float* end_tok     = (const float*)d_in[6];
    const float* Vw1 = (const float*)d_in[7];
    const float* Vb1 = (const float*)d_in[8];
    const float* Vw2 = (const float*)d_in[9];
    const float* Vb2 = (const float*)d_in[10];
    const float* Ew1 = (const float*)d_in[11];
    const float* Eb1 = (const float*)d_in[12];
    const float* Ew2 = (const float*)d_in[13];
    const float* Eb2 = (const float*)d_in[14];
    const float* Pw1 = (const float*)d_in[15];
    const float* Pb1 = (const float*)d_in[16];
    const float* Pw2 = (const float*)d_in[17];
    const float* Pb2 = (const float*)d_in[18];
    const float* Cw1 = (const float*)d_in[19];
    const float* Cb1 = (const float*)d_in[20];
    const float* Cw2 = (const float*)d_in[21];
    const float* Cb2 = (const float*)d_in[22];
    const float* Aw1 = (const float*)d_in[23];
    const float* Ab1 = (const float*)d_in[24];
    const float* Aw2 = (const float*)d_in[25];
    const float* Ab2 = (const float*)d_in[26];

    const int Nn = in_sizes[0] / 128;
    const int E  = in_sizes[1];

    float *hid, *sp, *sc, *bP, *bC;
    int *cs, *cp;
    cudaGetSymbolAddress((void**)&hid, g_hidden);
    cudaGetSymbolAddress((void**)&sp,  g_sp);
    cudaGetSymbolAddress((void**)&sc,  g_sc);
    cudaGetSymbolAddress((void**)&cs,  g_cnt_self);
    cudaGetSymbolAddress((void**)&cp,  g_cnt_par);
    cudaGetSymbolAddress((void**)&bP,  g_biasP);
    cudaGetSymbolAddress((void**)&bC,  g_biasC);
    uint32_t *v1, *v2, *p1, *p2, *c1, *c2, *a1, *a2;
    cudaGetSymbolAddress((void**)&v1, g_V1f);
    cudaGetSymbolAddress((void**)&v2, g_V2f);
    cudaGetSymbolAddress((void**)&p1, g_P1f);
    cudaGetSymbolAddress((void**)&p2, g_P2f);
    cudaGetSymbolAddress((void**)&c1, g_C1f);
    cudaGetSymbolAddress((void**)&c2, g_C2f);
    cudaGetSymbolAddress((void**)&a1, g_A1f);
    cudaGetSymbolAddress((void**)&a2, g_A2f);

    cudaFuncSetAttribute(mlp_v_tf, cudaFuncAttributeMaxDynamicSharedMemorySize, SMEM_ALL);
    cudaFuncSetAttribute(edge_tf,  cudaFuncAttributeMaxDynamicSharedMemorySize, SMEM_ALL);
    cudaFuncSetAttribute(node_tf,  cudaFuncAttributeMaxDynamicSharedMemorySize, SMEM_ALL);

    cudaMemsetAsync(cs, 0, (size_t)Nn * sizeof(int));
    cudaMemsetAsync(cp, 0, (size_t)Nn * sizeof(int));

    // launch #1: weight conversions (fp16 pairs) + degree counts
    {
        const int total = 196608 + E;
        prep_w<<<(total + 255) / 256, 256>>>(Vw1, Vw2, Pw1, Pw2, Cw1, Cw2, Aw1, Aw2,
                                             v1, v2, p1, p2, c1, c2, a1, a2,
                                             self_idx, parent_idx, cs, cp, E);
    }
    // launch #2
    prep_bias<<<1, 256>>>(Ew1, Eb1, Ew2, Eb2, Pw1, Pb1, Cw1, Cb1, bP, bC);

    const int gN = (Nn + 63) / 64;
    const int gE = (E + 63) / 64;
    // launch #3
    mlp_v_tf<<<gN, 256, SMEM_ALL>>>(batch_token, Vb1, Vb2, hid, Nn);

    for (int hop = 0; hop < 3; hop++) {
        cudaMemsetAsync(sp, 0, (size_t)Nn * 128 * sizeof(float));
        cudaMemsetAsync(sc, 0, (size_t)Nn * 128 * sizeof(float));
        // launches #4/#5 (hop0), #6 = edge (hop1) <- ncu capture target
        edge_tf<<<gE, 256, SMEM_ALL>>>(hid, self_idx, parent_idx,
                                       bP, Pb2, bC, Cb2, sp, sc, E);
        float* o = (hop == 2) ? (float*)d_out : hid;
        node_tf<<<gN, 256, SMEM_ALL>>>(hid, sp, sc, cs, cp,
                                       root_mask, leaf_mask, start_tok, end_tok,
                                       Ab1, Ab2, o, Nn);
    }
}